// round 16
// baseline (speedup 1.0000x reference)
#include <cuda_runtime.h>
#include <cuda_bf16.h>
#include <cuda_fp16.h>
#include <cstdint>
#include <cstddef>

// ============================================================================
// DeformableAttention: B=4, Lq=21760, DIM=256, NH=8, NP=4, HD=32
// Levels: (128,128),(64,64),(32,32),(16,16) -> Lv = 21760, starts 0/16384/20480/21504
// M = B*Lq = B*Lv = 87040
// Input GEMM: value CTAs cover full N=256 (A read once); logit CTAs N=96.
// Fused sample + output-projection kernel (1-term W_out, cp.async B).
// ============================================================================

#define M_TOTAL 87040
#define LQ 21760

__device__ __half  g_val16[(size_t)M_TOTAL * 256];
__device__ float   g_logit[(size_t)M_TOTAL * 96];    // 0-63 off, 64-95 attn
// fp16 transposed weights [slot][n*256+k]: 0=W_val, 1=W_out, 2=cat(W_off|W_attn|0)
__device__ __half  g_W16_hi[3][256 * 256];
__device__ float   g_bcat[128];

// ---------------------------------------------------------------------------
__device__ __forceinline__ uint32_t smem_to_u32(const void* p) {
    uint32_t a;
    asm("{ .reg .u64 t; cvta.to.shared.u64 t, %1; cvt.u32.u64 %0, t; }" : "=r"(a) : "l"(p));
    return a;
}
__device__ __forceinline__ uint32_t h2u(__half2 h) {
    return *reinterpret_cast<uint32_t*>(&h);
}
#define CP_ASYNC16(dst, src) \
    asm volatile("cp.async.cg.shared.global [%0], [%1], 16;" :: "r"(dst), "l"(src))
#define CP_COMMIT() asm volatile("cp.async.commit_group;" ::: "memory")
#define CP_WAIT0()  asm volatile("cp.async.wait_group 0;" ::: "memory")

__device__ __forceinline__ void ldm_x4(uint32_t addr, uint32_t& r0, uint32_t& r1,
                                       uint32_t& r2, uint32_t& r3) {
    asm volatile("ldmatrix.sync.aligned.m8n8.x4.shared.b16 {%0,%1,%2,%3}, [%4];"
                 : "=r"(r0), "=r"(r1), "=r"(r2), "=r"(r3) : "r"(addr));
}
__device__ __forceinline__ void ldm_x2(uint32_t addr, uint32_t& r0, uint32_t& r1) {
    asm volatile("ldmatrix.sync.aligned.m8n8.x2.shared.b16 {%0,%1}, [%2];"
                 : "=r"(r0), "=r"(r1) : "r"(addr));
}
__device__ __forceinline__ void mma_f16(float* d, const uint32_t* a, const uint32_t* b) {
    asm volatile("mma.sync.aligned.m16n8k16.row.col.f32.f16.f16.f32 "
                 "{%0,%1,%2,%3}, {%4,%5,%6,%7}, {%8,%9}, {%0,%1,%2,%3};"
                 : "+f"(d[0]), "+f"(d[1]), "+f"(d[2]), "+f"(d[3])
                 : "r"(a[0]), "r"(a[1]), "r"(a[2]), "r"(a[3]), "r"(b[0]), "r"(b[1]));
}

// ---------------------------------------------------------------------------
// prep: transpose + fp16 convert weights; concatenated logit bias
// ---------------------------------------------------------------------------
__global__ void __launch_bounds__(256) prep_kernel(
    const float* __restrict__ Wv, const float* __restrict__ Wo,
    const float* __restrict__ Woff, const float* __restrict__ Wattn,
    const float* __restrict__ boff, const float* __restrict__ battn)
{
    int k = blockIdx.x;       // 0..255
    int n = threadIdx.x;      // 0..255
    g_W16_hi[0][n * 256 + k] = __float2half_rn(Wv[k * 256 + n]);
    g_W16_hi[1][n * 256 + k] = __float2half_rn(Wo[k * 256 + n]);
    if (n < 128) {
        float v = 0.f;
        if (n < 64)      v = Woff[k * 64 + n];
        else if (n < 96) v = Wattn[k * 32 + (n - 64)];
        g_W16_hi[2][n * 256 + k] = __float2half_rn(v);
        if (k == 0) {
            float bb = 0.f;
            if (n < 64)      bb = boff[n];
            else if (n < 96) bb = battn[n - 64];
            g_bcat[n] = bb;
        }
    }
}

// ---------------------------------------------------------------------------
// Input GEMM. Grid = 1360*2; type = bid&1.
//  type 0: value projection, CTA N=256 (A read ONCE) -> g_val16 (fp16, +b_val)
//  type 1: logits (query @ cat(W_off|W_attn)) -> g_logit (96 cols; warps 0-2)
// CTA tile M=64, N=256 (value). 8 warps, warp tile 64x32 (4 m x 4 n mma tiles).
// K chunks of 64, double-buffered, B via cp.async. 1-term fp16.
// ---------------------------------------------------------------------------
#define STRB 144
#define SM_ROWPTR 0
#define SM_A0 512
#define SM_A1 (SM_A0 + 64 * STRB)           // +9216
#define SM_B0 (SM_A1 + 64 * STRB)           // 18944
#define SM_B1 (SM_B0 + 256 * STRB)          // +36864
#define SMEM_TOTAL (SM_B1 + 256 * STRB)     // 92672 B -> 2 CTAs/SM

__global__ void __launch_bounds__(256, 2) gemm_in(
    const float* __restrict__ f0, const float* __restrict__ f1,
    const float* __restrict__ f2, const float* __restrict__ f3,
    const float* __restrict__ query, const float* __restrict__ bval)
{
    extern __shared__ char smem[];
    const int t = threadIdx.x;
    const int wid = t >> 5, lane = t & 31;
    const int bid = blockIdx.x;
    const int type = bid & 1;            // 0: value; 1: logits
    const int m0 = (bid >> 1) * 64;

    const float** rowptr = (const float**)(smem + SM_ROWPTR);
    if (t < 64) {
        int r = m0 + t;
        const float* p;
        if (type == 0) {
            int b = r / LQ;
            int l = r - b * LQ;
            if (l < 16384)      p = f0 + ((size_t)b * 16384 + l) * 256;
            else if (l < 20480) p = f1 + ((size_t)b * 4096 + (l - 16384)) * 256;
            else if (l < 21504) p = f2 + ((size_t)b * 1024 + (l - 20480)) * 256;
            else                p = f3 + ((size_t)b * 256  + (l - 21504)) * 256;
        } else {
            p = query + (size_t)r * 256;
        }
        rowptr[t] = p;
    }
    __syncthreads();

    const __half* WtH = g_W16_hi[(type == 0) ? 0 : 2];
    const int nrows = (type == 0) ? 256 : 128;   // B rows to load per chunk

    uint32_t sb = smem_to_u32(smem);
    const uint32_t sA[2] = {sb + SM_A0, sb + SM_A1};
    const uint32_t sB[2] = {sb + SM_B0, sb + SM_B1};
    const int offA[2] = {SM_A0, SM_A1};

    const uint32_t a_row = lane & 15;
    const uint32_t a_koff = (lane >> 4) * 8;
    const uint32_t b_row = wid * 32 + (lane & 7);     // warp n-span 32
    const uint32_t b_koff = ((lane >> 3) & 1) * 8;

    float acc[4][4][4];                  // [m-tile][n-tile][frag]
    #pragma unroll
    for (int i = 0; i < 4; i++)
        #pragma unroll
        for (int j = 0; j < 4; j++)
            #pragma unroll
            for (int e = 0; e < 4; e++) acc[i][j][e] = 0.f;

    // chunk loader: B via cp.async (nrows), A via convert path
    auto load_chunk = [&](int c, int bf) {
        const int nslots = nrows * 8;            // uint4 slots (64k * 2B / 16)
        for (int idx = t; idx < nslots; idx += 256) {
            int r = idx >> 3, c8 = (idx & 7) * 8;
            CP_ASYNC16(sB[bf] + r * STRB + c8 * 2,
                       WtH + (size_t)r * 256 + c * 64 + c8);
        }
        CP_COMMIT();
        #pragma unroll
        for (int i = 0; i < 4; i++) {
            int idx = t + i * 256;               // 1024 float4 slots
            int r = idx >> 4, c4 = (idx & 15) * 4;
            float4 v = *(const float4*)(rowptr[r] + c * 64 + c4);
            uint32_t h01 = h2u(__floats2half2_rn(v.x, v.y));
            uint32_t h23 = h2u(__floats2half2_rn(v.z, v.w));
            *(uint2*)(smem + offA[bf] + r * STRB + c4 * 2) = make_uint2(h01, h23);
        }
    };

    load_chunk(0, 0);
    CP_WAIT0();
    __syncthreads();

    for (int c = 0; c < 4; c++) {
        if (c < 3) load_chunk(c + 1, (c + 1) & 1);

        if (type == 0 || wid < 3) {   // logits: only cols 0-95 -> warps 0-2
            const uint32_t sAc = sA[c & 1], sBc = sB[c & 1];
            #pragma unroll
            for (int ks = 0; ks < 4; ks++) {
                const int k0 = ks * 16;
                uint32_t a[4][4], bh[4][2];
                #pragma unroll
                for (int mt = 0; mt < 4; mt++) {
                    uint32_t off = (a_row + mt * 16) * STRB + (k0 + a_koff) * 2;
                    ldm_x4(sAc + off, a[mt][0], a[mt][1], a[mt][2], a[mt][3]);
                }
                #pragma unroll
                for (int nt = 0; nt < 4; nt++) {
                    uint32_t off = (b_row + nt * 8) * STRB + (k0 + b_koff) * 2;
                    ldm_x2(sBc + off, bh[nt][0], bh[nt][1]);
                }
                #pragma unroll
                for (int mt = 0; mt < 4; mt++)
                    #pragma unroll
                    for (int nt = 0; nt < 4; nt++)
                        mma_f16(acc[mt][nt], a[mt], bh[nt]);
            }
        }
        CP_WAIT0();
        __syncthreads();
    }

    // ---- epilogue ----
    const int col_base = wid * 32;
    #pragma unroll
    for (int nt = 0; nt < 4; nt++) {
        const int col = col_base + nt * 8 + (lane & 3) * 2;
        if (type == 1 && col >= 96) continue;
        float2 bv;
        if (type == 1) bv = *(const float2*)(g_bcat + col);
        else           bv = *(const float2*)(bval + col);
        #pragma unroll
        for (int mt = 0; mt < 4; mt++) {
            int r0 = m0 + mt * 16 + (lane >> 2);
            float2 o0, o1;
            o0.x = acc[mt][nt][0] + bv.x; o0.y = acc[mt][nt][1] + bv.y;
            o1.x = acc[mt][nt][2] + bv.x; o1.y = acc[mt][nt][3] + bv.y;
            if (type == 0) {
                *(__half2*)(g_val16 + (size_t)r0 * 256 + col)       = __floats2half2_rn(o0.x, o0.y);
                *(__half2*)(g_val16 + (size_t)(r0 + 8) * 256 + col) = __floats2half2_rn(o1.x, o1.y);
            } else {
                *(float2*)(g_logit + (size_t)r0 * 96 + col)       = o0;
                *(float2*)(g_logit + (size_t)(r0 + 8) * 96 + col) = o1;
            }
        }
    }
}

// ----------------------------------------------------------------------------
// FUSED sample + output projection (3 CTAs/SM). Block = 64 queries, 256 threads.
// Phase A/B: softmax+index+gather -> smem mid (fp16, ldmatrix layout).
// Phase C: out = mid @ W_out (1-term fp16) + b_out, double-buffered cp.async B.
// ----------------------------------------------------------------------------
#define ASTR 528                    // A row stride bytes (256 halves + 8 pad)
#define FS_A     0                  // 64 * 528 = 33792
#define FS_SCR   33792
#define FS_LOGIT (FS_SCR)           // 32*96*4 = 12288
#define FS_WS    (FS_SCR + 12288)   // 32*8*16*4 = 16384
#define FS_VROW  (FS_SCR + 28672)   // 32*8*16*2 = 8192
#define FS_REFS  (FS_SCR + 36864)   // 32*8*4 = 1024
#define FS_B0    (FS_SCR)           // phase C alias: 128*144 = 18432
#define FS_B1    (FS_SCR + 18432)   // 18432 -> ends 36864 < 37888
#define FUSED_SMEM (FS_SCR + 37888) // 71680 B

__global__ void __launch_bounds__(256, 3) fused_kernel(
    const float* __restrict__ refpts,
    const float* __restrict__ bout,
    float* __restrict__ out)
{
    extern __shared__ char smem[];
    const int t = threadIdx.x;
    const int wid = t >> 5, lane = t & 31;
    const long long gq0 = (long long)blockIdx.x * 64;
    const int b = (int)(gq0 / LQ);            // constant per block (64 | LQ)

    float (*logit)[96]     = (float (*)[96])(smem + FS_LOGIT);
    float (*ws)[8][16]     = (float (*)[8][16])(smem + FS_WS);
    uint16_t (*vrl)[8][16] = (uint16_t (*)[8][16])(smem + FS_VROW);
    float (*refs)[4][2]    = (float (*)[4][2])(smem + FS_REFS);
    uint32_t sb = smem_to_u32(smem);

    // ================= Phase A/B: sample 2 halves of 32 rows =================
    for (int half = 0; half < 2; half++) {
        const long long q0 = gq0 + half * 32;

        #pragma unroll
        for (int i = 0; i < 3; i++) {
            int idx = t + i * 256;            // 768 float4 slots
            int r = idx / 24, cq = (idx % 24) * 4;
            CP_ASYNC16(sb + FS_LOGIT + (r * 96 + cq) * 4,
                       g_logit + (q0 + r) * 96 + cq);
        }
        CP_COMMIT();
        ((float*)refs)[t] = refpts[q0 * 8 + t];
        CP_WAIT0();
        __syncthreads();

        // softmax + indices + weight expansion: thread -> (row, head)
        {
            const int r = t >> 3, h = t & 7;
            float l[4];
            float mx = -1e30f;
            #pragma unroll
            for (int p = 0; p < 4; p++) { l[p] = logit[r][64 + h * 4 + p]; mx = fmaxf(mx, l[p]); }
            float s = 0.f;
            #pragma unroll
            for (int p = 0; p < 4; p++) { l[p] = expf(l[p] - mx); s += l[p]; }
            float inv = 1.0f / s;

            const int DIMS[4]  = {128, 64, 32, 16};
            const int START[4] = {0, 16384, 20480, 21504};
            #pragma unroll
            for (int lvl = 0; lvl < 4; lvl++) {
                float rx = refs[r][lvl][0];
                float ry = refs[r][lvl][1];
                int Wl = DIMS[lvl];
                #pragma unroll
                for (int p = 0; p < 4; p++) {
                    float ox = logit[r][h * 8 + p * 2 + 0];
                    float oy = logit[r][h * 8 + p * 2 + 1];
                    float sx = fminf(fmaxf(rx + ox, 0.f), 1.f);
                    float sy = fminf(fmaxf(ry + oy, 0.f), 1.f);
                    int x0 = (int)floorf(sx * (float)(Wl - 1));
                    int y0 = (int)floorf(sy * (float)(Wl - 1));
                    vrl[r][h][p * 4 + lvl] = (uint16_t)(START[lvl] + y0 * Wl + x0);
                    ws[r][h][p * 4 + lvl] = l[p] * inv;
                }
            }
        }
        __syncthreads();

        // gather -> mid into A-smem (fp16, row-major stride ASTR)
        {
            const int h = lane >> 2;             // 0..7
            const int c8 = (lane & 3) * 8;       // channel group within head
            const int coff = h * 32 + c8;
            const size_t vbase = (size_t)b * LQ;
            #pragma unroll
            for (int rw = 0; rw < 4; rw++) {
                const int r = wid * 4 + rw;
                const uint16_t* vr = vrl[r][h];
                const float* wsv = ws[r][h];
                float acc[8] = {0.f, 0.f, 0.f, 0.f, 0.f, 0.f, 0.f, 0.f};
                #pragma unroll
                for (int s = 0; s < 16; s++) {
                    uint4 u = *(const uint4*)(g_val16 + (vbase + vr[s]) * 256 + coff);
                    float wgt = wsv[s];
                    const __half2* hp = (const __half2*)&u;
                    #pragma unroll
                    for (int e = 0; e < 4; e++) {
                        float2 f = __half22float2(hp[e]);
                        acc[2 * e]     += wgt * f.x;
                        acc[2 * e + 1] += wgt * f.y;
                    }
                }
                __half2 o[4];
                #pragma unroll
                for (int e = 0; e < 4; e++)
                    o[e] = __floats2half2_rn(acc[2 * e], acc[2 * e + 1]);
                *(uint4*)(smem + FS_A + (half * 32 + r) * ASTR + coff * 2) = *(uint4*)o;
            }
        }
        __syncthreads();   // scratch free before next half / phase C B writes
    }

    // ================= Phase C: out = mid @ W_out + b_out =================
    const uint32_t sA = sb + FS_A;
    const uint32_t sB[2] = {sb + FS_B0, sb + FS_B1};
    const __half* WtH = g_W16_hi[1];

    const uint32_t a_row = lane & 15;
    const uint32_t a_koff = (lane >> 4) * 8;
    const uint32_t b_row = wid * 16 + (lane & 7);
    const uint32_t b_koff = ((lane >> 3) & 1) * 8;
    const int m0 = (int)gq0;

    for (int nh = 0; nh < 2; nh++) {
        const int n0 = nh * 128;
        float acc[4][2][4];
        #pragma unroll
        for (int i = 0; i < 4; i++)
            #pragma unroll
            for (int j = 0; j < 2; j++)
                #pragma unroll
                for (int e = 0; e < 4; e++) acc[i][j][e] = 0.f;

        auto load_b = [&](int c, int bf) {
            #pragma unroll
            for (int i = 0; i < 4; i++) {
                int idx = t + i * 256;                // 1024 uint4 slots
                int r = idx >> 3, c8 = (idx & 7) * 8;
                CP_ASYNC16(sB[bf] + r * STRB + c8 * 2,
                           WtH + (size_t)(n0 + r) * 256 + c * 64 + c8);
            }
            CP_COMMIT();
        };

        load_b(0, 0);
        CP_WAIT0();
        __syncthreads();

        for (int c = 0; c < 4; c++) {
            if (c < 3) load_b(c + 1, (c + 1) & 1);

            const uint32_t sBc = sB[c & 1];
            #pragma unroll
            for (int ks = 0; ks < 4; ks++) {
                const int k0 = c * 64 + ks * 16;
                uint32_t a[4][4], bh[2][2];
                #pragma unroll
                for (int mt = 0; mt < 4; mt++) {
                    uint32_t off = (a_row + mt * 16) * ASTR + (k0 + a_koff) * 2;
                    ldm_x4(sA + off, a[mt][0], a[mt][1], a[mt][2], a[mt][3]);
                }
                #pragma unroll
                for (int nt = 0; nt < 2; nt++) {
                    uint32_t off = (b_row + nt * 8) * STRB + (ks * 16 + b_koff) * 2;
                    ldm_x2(sBc + off, bh[nt][0], bh[nt][1]);
                }
                #pragma unroll
                for (int mt = 0; mt < 4; mt++)
                    #pragma unroll
                    for (int nt = 0; nt < 2; nt++)
                        mma_f16(acc[mt][nt], a[mt], bh[nt]);
            }
            CP_WAIT0();
            __syncthreads();
        }

        // epilogue for this n-half
        const int col_base = n0 + wid * 16;
        #pragma unroll
        for (int nt = 0; nt < 2; nt++) {
            const int col = col_base + nt * 8 + (lane & 3) * 2;
            float2 bv = *(const float2*)(bout + col);
            #pragma unroll
            for (int mt = 0; mt < 4; mt++) {
                int r0 = m0 + mt * 16 + (lane >> 2);
                float2 o0, o1;
                o0.x = acc[mt][nt][0] + bv.x; o0.y = acc[mt][nt][1] + bv.y;
                o1.x = acc[mt][nt][2] + bv.x; o1.y = acc[mt][nt][3] + bv.y;
                *(float2*)(out + (size_t)r0 * 256 + col)       = o0;
                *(float2*)(out + (size_t)(r0 + 8) * 256 + col) = o1;
            }
        }
    }
}

// ----------------------------------------------------------------------------
extern "C" void kernel_launch(void* const* d_in, const int* in_sizes, int n_in,
                              void* d_out, int out_size)
{
    (void)in_sizes; (void)n_in; (void)out_size;
    const float* query  = (const float*)d_in[0];
    const float* refpts = (const float*)d_in[1];
    const float* f0     = (const float*)d_in[2];
    const float* f1     = (const float*)d_in[3];
    const float* f2     = (const float*)d_in[4];
    const float* f3     = (const float*)d_in[5];
    const float* W_off  = (const float*)d_in[6];
    const float* b_off  = (const float*)d_in[7];
    const float* W_attn = (const float*)d_in[8];
    const float* b_attn = (const float*)d_in[9];
    const float* W_val  = (const float*)d_in[10];
    const float* b_val  = (const float*)d_in[11];
    const float* W_out  = (const float*)d_in[12];
    const float* b_out  = (const float*)d_in[13];
    float* out = (float*)d_out;

    cudaFuncSetAttribute(gemm_in, cudaFuncAttributeMaxDynamicSharedMemorySize, SMEM_TOTAL);
    cudaFuncSetAttribute(fused_kernel, cudaFuncAttributeMaxDynamicSharedMemorySize, FUSED_SMEM);

    prep_kernel<<<256, 256>>>(W_val, W_out, W_off, W_attn, b_off, b_attn);

    // merged: value projection (N=256, A read once) + logits, interleaved by bid&1
    gemm_in<<<(M_TOTAL / 64) * 2, 256, SMEM_TOTAL>>>(f0, f1, f2, f3, query, b_val);
    // fused softmax + gather + output projection -> out
    fused_kernel<<<M_TOTAL / 64, 256, FUSED_SMEM>>>(refpts, b_out, out);
}

// round 17
// speedup vs baseline: 1.0513x; 1.0513x over previous
#include <cuda_runtime.h>
#include <cuda_bf16.h>
#include <cuda_fp16.h>
#include <cstdint>
#include <cstddef>

// ============================================================================
// DeformableAttention: B=4, Lq=21760, DIM=256, NH=8, NP=4, HD=32
// Levels: (128,128),(64,64),(32,32),(16,16) -> Lv = 21760, starts 0/16384/20480/21504
// M = B*Lq = B*Lv = 87040
// Merged input GEMM (double-buffered, cp.async B), then fused
// sample + output-projection kernel (1-term W_out, cp.async B).
// ============================================================================

#define M_TOTAL 87040
#define LQ 21760

__device__ __half  g_val16[(size_t)M_TOTAL * 256];
__device__ float   g_logit[(size_t)M_TOTAL * 96];    // 0-63 off, 64-95 attn
// fp16 transposed weights [slot][n*256+k]: 0=W_val, 1=W_out, 2=cat(W_off|W_attn|0)
__device__ __half  g_W16_hi[3][256 * 256];
__device__ float   g_bcat[128];

// ---------------------------------------------------------------------------
__device__ __forceinline__ uint32_t smem_to_u32(const void* p) {
    uint32_t a;
    asm("{ .reg .u64 t; cvta.to.shared.u64 t, %1; cvt.u32.u64 %0, t; }" : "=r"(a) : "l"(p));
    return a;
}
__device__ __forceinline__ uint32_t h2u(__half2 h) {
    return *reinterpret_cast<uint32_t*>(&h);
}
#define CP_ASYNC16(dst, src) \
    asm volatile("cp.async.cg.shared.global [%0], [%1], 16;" :: "r"(dst), "l"(src))
#define CP_COMMIT() asm volatile("cp.async.commit_group;" ::: "memory")
#define CP_WAIT0()  asm volatile("cp.async.wait_group 0;" ::: "memory")
#define CP_WAIT1()  asm volatile("cp.async.wait_group 1;" ::: "memory")

__device__ __forceinline__ void ldm_x4(uint32_t addr, uint32_t& r0, uint32_t& r1,
                                       uint32_t& r2, uint32_t& r3) {
    asm volatile("ldmatrix.sync.aligned.m8n8.x4.shared.b16 {%0,%1,%2,%3}, [%4];"
                 : "=r"(r0), "=r"(r1), "=r"(r2), "=r"(r3) : "r"(addr));
}
__device__ __forceinline__ void ldm_x2(uint32_t addr, uint32_t& r0, uint32_t& r1) {
    asm volatile("ldmatrix.sync.aligned.m8n8.x2.shared.b16 {%0,%1}, [%2];"
                 : "=r"(r0), "=r"(r1) : "r"(addr));
}
__device__ __forceinline__ void mma_f16(float* d, const uint32_t* a, const uint32_t* b) {
    asm volatile("mma.sync.aligned.m16n8k16.row.col.f32.f16.f16.f32 "
                 "{%0,%1,%2,%3}, {%4,%5,%6,%7}, {%8,%9}, {%0,%1,%2,%3};"
                 : "+f"(d[0]), "+f"(d[1]), "+f"(d[2]), "+f"(d[3])
                 : "r"(a[0]), "r"(a[1]), "r"(a[2]), "r"(a[3]), "r"(b[0]), "r"(b[1]));
}

// ---------------------------------------------------------------------------
// prep: transpose + fp16 convert weights; concatenated logit bias
// ---------------------------------------------------------------------------
__global__ void __launch_bounds__(256) prep_kernel(
    const float* __restrict__ Wv, const float* __restrict__ Wo,
    const float* __restrict__ Woff, const float* __restrict__ Wattn,
    const float* __restrict__ boff, const float* __restrict__ battn)
{
    int k = blockIdx.x;       // 0..255
    int n = threadIdx.x;      // 0..255
    g_W16_hi[0][n * 256 + k] = __float2half_rn(Wv[k * 256 + n]);
    g_W16_hi[1][n * 256 + k] = __float2half_rn(Wo[k * 256 + n]);
    if (n < 128) {
        float v = 0.f;
        if (n < 64)      v = Woff[k * 64 + n];
        else if (n < 96) v = Wattn[k * 32 + (n - 64)];
        g_W16_hi[2][n * 256 + k] = __float2half_rn(v);
        if (k == 0) {
            float bb = 0.f;
            if (n < 64)      bb = boff[n];
            else if (n < 96) bb = battn[n - 64];
            g_bcat[n] = bb;
        }
    }
}

// ---------------------------------------------------------------------------
// Merged input GEMM, double-buffered + cp.async B. Grid = 1360*3; type = bid%3.
//  type 0/1: value projection, n0 = type*128 -> g_val16 (fp16, +b_val)
//  type 2  : logits (query @ cat(W_off|W_attn)) -> g_logit (96 cols; 96 B-rows)
// ---------------------------------------------------------------------------
#define STRB 144
#define SM_ROWPTR 0
#define SM_A0 512
#define SM_A1 (SM_A0 + 64 * STRB)          // 9728
#define SM_B0 (SM_A1 + 64 * STRB)          // 18944
#define SM_B1 (SM_B0 + 128 * STRB)         // 37376
#define SMEM_TOTAL (SM_B1 + 128 * STRB)    // 55808 B

__global__ void __launch_bounds__(256, 3) gemm_in(
    const float* __restrict__ f0, const float* __restrict__ f1,
    const float* __restrict__ f2, const float* __restrict__ f3,
    const float* __restrict__ query, const float* __restrict__ bval)
{
    extern __shared__ char smem[];
    const int t = threadIdx.x;
    const int wid = t >> 5, lane = t & 31;
    const int bid = blockIdx.x;
    const int type = bid % 3;            // 0,1: value halves; 2: logits
    const int m0 = (bid / 3) * 64;
    const int n0 = (type < 2) ? type * 128 : 0;

    const float** rowptr = (const float**)(smem + SM_ROWPTR);
    if (t < 64) {
        int r = m0 + t;
        const float* p;
        if (type < 2) {
            int b = r / LQ;
            int l = r - b * LQ;
            if (l < 16384)      p = f0 + ((size_t)b * 16384 + l) * 256;
            else if (l < 20480) p = f1 + ((size_t)b * 4096 + (l - 16384)) * 256;
            else if (l < 21504) p = f2 + ((size_t)b * 1024 + (l - 20480)) * 256;
            else                p = f3 + ((size_t)b * 256  + (l - 21504)) * 256;
        } else {
            p = query + (size_t)r * 256;
        }
        rowptr[t] = p;
    }
    __syncthreads();

    const __half* WtH = g_W16_hi[(type < 2) ? 0 : 2];
    const int bslots = (type < 2) ? 1024 : 768;   // uint4 slots (128 vs 96 rows)

    uint32_t sb = smem_to_u32(smem);
    const uint32_t sA[2] = {sb + SM_A0, sb + SM_A1};
    const uint32_t sB[2] = {sb + SM_B0, sb + SM_B1};
    const int offA[2] = {SM_A0, SM_A1};

    const uint32_t a_row = lane & 15;
    const uint32_t a_koff = (lane >> 4) * 8;
    const uint32_t b_row = wid * 16 + (lane & 7);
    const uint32_t b_koff = ((lane >> 3) & 1) * 8;

    float acc[4][2][4];
    #pragma unroll
    for (int i = 0; i < 4; i++)
        #pragma unroll
        for (int j = 0; j < 2; j++)
            #pragma unroll
            for (int e = 0; e < 4; e++) acc[i][j][e] = 0.f;

    // chunk loader: B via cp.async, A via convert path
    auto load_chunk = [&](int c, int bf) {
        for (int idx = t; idx < bslots; idx += 256) {
            int r = idx >> 3, c8 = (idx & 7) * 8;
            CP_ASYNC16(sB[bf] + r * STRB + c8 * 2,
                       WtH + (size_t)(n0 + r) * 256 + c * 64 + c8);
        }
        CP_COMMIT();
        #pragma unroll
        for (int i = 0; i < 4; i++) {
            int idx = t + i * 256;                // 1024 float4 slots
            int r = idx >> 4, c4 = (idx & 15) * 4;
            float4 v = *(const float4*)(rowptr[r] + c * 64 + c4);
            uint32_t h01 = h2u(__floats2half2_rn(v.x, v.y));
            uint32_t h23 = h2u(__floats2half2_rn(v.z, v.w));
            *(uint2*)(smem + offA[bf] + r * STRB + c4 * 2) = make_uint2(h01, h23);
        }
    };

    load_chunk(0, 0);
    CP_WAIT0();
    __syncthreads();

    for (int c = 0; c < 4; c++) {
        if (c < 3) load_chunk(c + 1, (c + 1) & 1);

        if (type < 2 || wid < 6) {   // logits: cols 96-127 zero, warps 6-7 idle
            const uint32_t sAc = sA[c & 1], sBc = sB[c & 1];
            #pragma unroll
            for (int ks = 0; ks < 4; ks++) {
                const int k0 = ks * 16;
                uint32_t a[4][4], bh[2][2];
                #pragma unroll
                for (int mt = 0; mt < 4; mt++) {
                    uint32_t off = (a_row + mt * 16) * STRB + (k0 + a_koff) * 2;
                    ldm_x4(sAc + off, a[mt][0], a[mt][1], a[mt][2], a[mt][3]);
                }
                #pragma unroll
                for (int nt = 0; nt < 2; nt++) {
                    uint32_t off = (b_row + nt * 8) * STRB + (k0 + b_koff) * 2;
                    ldm_x2(sBc + off, bh[nt][0], bh[nt][1]);
                }
                #pragma unroll
                for (int mt = 0; mt < 4; mt++)
                    #pragma unroll
                    for (int nt = 0; nt < 2; nt++)
                        mma_f16(acc[mt][nt], a[mt], bh[nt]);
            }
        }
        if (c < 3) { CP_WAIT0(); }
        __syncthreads();
    }

    // ---- epilogue ----
    const int col_base = n0 + wid * 16;
    #pragma unroll
    for (int nt = 0; nt < 2; nt++) {
        const int col = col_base + nt * 8 + (lane & 3) * 2;
        if (type == 2 && col >= 96) continue;
        float2 bv;
        if (type == 2) bv = *(const float2*)(g_bcat + col);
        else           bv = *(const float2*)(bval + col);
        #pragma unroll
        for (int mt = 0; mt < 4; mt++) {
            int r0 = m0 + mt * 16 + (lane >> 2);
            float2 o0, o1;
            o0.x = acc[mt][nt][0] + bv.x; o0.y = acc[mt][nt][1] + bv.y;
            o1.x = acc[mt][nt][2] + bv.x; o1.y = acc[mt][nt][3] + bv.y;
            if (type < 2) {
                *(__half2*)(g_val16 + (size_t)r0 * 256 + col)       = __floats2half2_rn(o0.x, o0.y);
                *(__half2*)(g_val16 + (size_t)(r0 + 8) * 256 + col) = __floats2half2_rn(o1.x, o1.y);
            } else {
                *(float2*)(g_logit + (size_t)r0 * 96 + col)       = o0;
                *(float2*)(g_logit + (size_t)(r0 + 8) * 96 + col) = o1;
            }
        }
    }
}

// ----------------------------------------------------------------------------
// FUSED sample + output projection (3 CTAs/SM). Block = 64 queries, 256 threads.
// Phase A/B: softmax+index+gather -> smem mid (fp16, ldmatrix layout).
// Double-buffered logit tiles: next half's logits prefetched during the gather.
// Phase C: out = mid @ W_out (1-term fp16) + b_out, double-buffered cp.async B.
// ----------------------------------------------------------------------------
#define ASTR 528                    // A row stride bytes (256 halves + 8 pad)
#define FS_A     0                  // 64 * 528 = 33792
#define FS_SCR   33792
#define FS_LOG0  (FS_SCR)           // 32*96*4 = 12288
#define FS_WS    (FS_SCR + 12288)   // 32*8*16*4 = 16384
#define FS_VROW  (FS_SCR + 28672)   // 32*8*16*2 = 8192
#define FS_REFS  (FS_SCR + 36864)   // 32*8*4 = 1024
#define FS_B0    (FS_SCR)           // phase C alias: 128*144 = 18432
#define FS_B1    (FS_SCR + 18432)   // ends 36864 < 37888
#define FUSED_SMEM (FS_SCR + 37888) // 71680 B

__global__ void __launch_bounds__(256, 3) fused_kernel(
    const float* __restrict__ refpts,
    const float* __restrict__ bout,
    float* __restrict__ out)
{
    extern __shared__ char smem[];
    const int t = threadIdx.x;
    const int wid = t >> 5, lane = t & 31;
    const long long gq0 = (long long)blockIdx.x * 64;
    const int b = (int)(gq0 / LQ);            // constant per block (64 | LQ)

    float (*logit)[96]     = (float (*)[96])(smem + FS_LOG0);
    float (*ws)[8][16]     = (float (*)[8][16])(smem + FS_WS);
    uint16_t (*vrl)[8][16] = (uint16_t (*)[8][16])(smem + FS_VROW);
    float (*refs)[4][2]    = (float (*)[4][2])(smem + FS_REFS);
    uint32_t sb = smem_to_u32(smem);

    // ================= Phase A/B: sample 2 halves of 32 rows =================
    for (int half = 0; half < 2; half++) {
        const long long q0 = gq0 + half * 32;

        #pragma unroll
        for (int i = 0; i < 3; i++) {
            int idx = t + i * 256;            // 768 float4 slots
            int r = idx / 24, cq = (idx % 24) * 4;
            CP_ASYNC16(sb + FS_LOG0 + (r * 96 + cq) * 4,
                       g_logit + (q0 + r) * 96 + cq);
        }
        CP_COMMIT();
        ((float*)refs)[t] = refpts[q0 * 8 + t];
        CP_WAIT0();
        __syncthreads();

        // softmax + indices + weight expansion: thread -> (row, head)
        {
            const int r = t >> 3, h = t & 7;
            float l[4];
            float mx = -1e30f;
            #pragma unroll
            for (int p = 0; p < 4; p++) { l[p] = logit[r][64 + h * 4 + p]; mx = fmaxf(mx, l[p]); }
            float s = 0.f;
            #pragma unroll
            for (int p = 0; p < 4; p++) { l[p] = expf(l[p] - mx); s += l[p]; }
            float inv = 1.0f / s;

            const int DIMS[4]  = {128, 64, 32, 16};
            const int START[4] = {0, 16384, 20480, 21504};
            #pragma unroll
            for (int lvl = 0; lvl < 4; lvl++) {
                float rx = refs[r][lvl][0];
                float ry = refs[r][lvl][1];
                int Wl = DIMS[lvl];
                #pragma unroll
                for (int p = 0; p < 4; p++) {
                    float ox = logit[r][h * 8 + p * 2 + 0];
                    float oy = logit[r][h * 8 + p * 2 + 1];
                    float sx = fminf(fmaxf(rx + ox, 0.f), 1.f);
                    float sy = fminf(fmaxf(ry + oy, 0.f), 1.f);
                    int x0 = (int)floorf(sx * (float)(Wl - 1));
                    int y0 = (int)floorf(sy * (float)(Wl - 1));
                    vrl[r][h][p * 4 + lvl] = (uint16_t)(START[lvl] + y0 * Wl + x0);
                    ws[r][h][p * 4 + lvl] = l[p] * inv;
                }
            }
        }
        __syncthreads();

        // gather -> mid into A-smem (fp16, row-major stride ASTR)
        {
            const int h = lane >> 2;             // 0..7
            const int c8 = (lane & 3) * 8;       // channel group within head
            const int coff = h * 32 + c8;
            const size_t vbase = (size_t)b * LQ;
            #pragma unroll
            for (int rw = 0; rw < 4; rw++) {
                const int r = wid * 4 + rw;
                const uint16_t* vr = vrl[r][h];
                const float* wsv = ws[r][h];
                float acc[8] = {0.f, 0.f, 0.f, 0.f, 0.f, 0.f, 0.f, 0.f};
                #pragma unroll
                for (int s = 0; s < 16; s++) {
                    uint4 u = *(const uint4*)(g_val16 + (vbase + vr[s]) * 256 + coff);
                    float wgt = wsv[s];
                    const __half2* hp = (const __half2*)&u;
                    #pragma unroll
                    for (int e = 0; e < 4; e++) {
                        float2 f = __half22float2(hp[e]);
                        acc[2 * e]     += wgt * f.x;
                        acc[2 * e + 1] += wgt * f.y;
                    }
                }
                __half2 o[4];
                #pragma unroll
                for (int e = 0; e < 4; e++)
                    o[e] = __floats2half2_rn(acc[2 * e], acc[2 * e + 1]);
                *(uint4*)(smem + FS_A + (half * 32 + r) * ASTR + coff * 2) = *(uint4*)o;
            }
        }
        __syncthreads();   // scratch free before next half / phase C B writes
    }

    // ================= Phase C: out = mid @ W_out + b_out =================
    const uint32_t sA = sb + FS_A;
    const uint32_t sB[2] = {sb + FS_B0, sb + FS_B1};
    const __half* WtH = g_W16_hi[1];

    const uint32_t a_row = lane & 15;
    const uint32_t a_koff = (lane >> 4) * 8;
    const uint32_t b_row = wid * 16 + (lane & 7);
    const uint32_t b_koff = ((lane >> 3) & 1) * 8;
    const int m0 = (int)gq0;

    for (int nh = 0; nh < 2; nh++) {
        const int n0 = nh * 128;
        float acc[4][2][4];
        #pragma unroll
        for (int i = 0; i < 4; i++)
            #pragma unroll
            for (int j = 0; j < 2; j++)
                #pragma unroll
                for (int e = 0; e < 4; e++) acc[i][j][e] = 0.f;

        auto load_b = [&](int c, int bf) {
            #pragma unroll
            for (int i = 0; i < 4; i++) {
                int idx = t + i * 256;                // 1024 uint4 slots
                int r = idx >> 3, c8 = (idx & 7) * 8;
                CP_ASYNC16(sB[bf] + r * STRB + c8 * 2,
                           WtH + (size_t)(n0 + r) * 256 + c * 64 + c8);
            }
            CP_COMMIT();
        };

        load_b(0, 0);
        CP_WAIT0();
        __syncthreads();

        for (int c = 0; c < 4; c++) {
            if (c < 3) load_b(c + 1, (c + 1) & 1);

            const uint32_t sBc = sB[c & 1];
            #pragma unroll
            for (int ks = 0; ks < 4; ks++) {
                const int k0 = c * 64 + ks * 16;
                uint32_t a[4][4], bh[2][2];
                #pragma unroll
                for (int mt = 0; mt < 4; mt++) {
                    uint32_t off = (a_row + mt * 16) * ASTR + (k0 + a_koff) * 2;
                    ldm_x4(sA + off, a[mt][0], a[mt][1], a[mt][2], a[mt][3]);
                }
                #pragma unroll
                for (int nt = 0; nt < 2; nt++) {
                    uint32_t off = (b_row + nt * 8) * STRB + (ks * 16 + b_koff) * 2;
                    ldm_x2(sBc + off, bh[nt][0], bh[nt][1]);
                }
                #pragma unroll
                for (int mt = 0; mt < 4; mt++)
                    #pragma unroll
                    for (int nt = 0; nt < 2; nt++)
                        mma_f16(acc[mt][nt], a[mt], bh[nt]);
            }
            if (c < 3) { CP_WAIT0(); }
            __syncthreads();
        }

        // epilogue for this n-half
        const int col_base = n0 + wid * 16;
        #pragma unroll
        for (int nt = 0; nt < 2; nt++) {
            const int col = col_base + nt * 8 + (lane & 3) * 2;
            float2 bv = *(const float2*)(bout + col);
            #pragma unroll
            for (int mt = 0; mt < 4; mt++) {
                int r0 = m0 + mt * 16 + (lane >> 2);
                float2 o0, o1;
                o0.x = acc[mt][nt][0] + bv.x; o0.y = acc[mt][nt][1] + bv.y;
                o1.x = acc[mt][nt][2] + bv.x; o1.y = acc[mt][nt][3] + bv.y;
                *(float2*)(out + (size_t)r0 * 256 + col)       = o0;
                *(float2*)(out + (size_t)(r0 + 8) * 256 + col) = o1;
            }
        }
    }
}

// ----------------------------------------------------------------------------
extern "C" void kernel_launch(void* const* d_in, const int* in_sizes, int n_in,
                              void* d_out, int out_size)
{
    (void)in_sizes; (void)n_in; (void)out_size;
    const float* query  = (const float*)d_in[0];
    const float* refpts = (const float*)d_in[1];
    const float* f0     = (const float*)d_in[2];
    const float* f1     = (const float*)d_in[3];
    const float* f2     = (const float*)d_in[4];
    const float* f3     = (const float*)d_in[5];
    const float* W_off  = (const float*)d_in[6];
    const float* b_off  = (const float*)d_in[7];
    const float* W_attn = (const float*)d_in[8];
    const float* b_attn = (const float*)d_in[9];
    const float* W_val  = (const float*)d_in[10];
    const float* b_val  = (const float*)d_in[11];
    const float* W_out  = (const float*)d_in[12];
    const float* b_out  = (const float*)d_in[13];
    float* out = (float*)d_out;

    cudaFuncSetAttribute(gemm_in, cudaFuncAttributeMaxDynamicSharedMemorySize, SMEM_TOTAL);
    cudaFuncSetAttribute(fused_kernel, cudaFuncAttributeMaxDynamicSharedMemorySize, FUSED_SMEM);

    prep_kernel<<<256, 256>>>(W_val, W_out, W_off, W_attn, b_off, b_attn);

    // merged: value projection (2 n-halves) + logits, interleaved by bid%3
    gemm_in<<<(M_TOTAL / 64) * 3, 256, SMEM_TOTAL>>>(f0, f1, f2, f3, query, b_val);
    // fused softmax + gather + output projection -> out
    fused_kernel<<<M_TOTAL / 64, 256, FUSED_SMEM>>>(refpts, b_out, out);
}